// round 5
// baseline (speedup 1.0000x reference)
#include <cuda_runtime.h>
#include <cuda_bf16.h>
#include <cstddef>

// Problem constants
#define NN    4096          // nodes
#define BB    4             // batch
#define CC    32            // channels
#define TT    12            // time
#define FF    1536          // BT*C features per node
#define DCAP  256           // per-row neighbor capacity (max degree ~120)

// ---------------- scratch (device globals; no allocations allowed) ----------
__device__ float g_dinv[NN];
__device__ int   g_len [NN];
__device__ int   g_col [NN * DCAP];
__device__ float         g_h  [(size_t)NN * FF];   // fp32 master
__device__ float         g_t1 [(size_t)NN * FF];
__device__ float         g_tx2[(size_t)NN * FF];
__device__ __nv_bfloat16 g_hb [(size_t)NN * FF];   // bf16 gather shadows
__device__ __nv_bfloat16 g_t1b[(size_t)NN * FF];

// ---------------- K1: CSR build + degree (adj is exactly {0,1}) --------------
__global__ void k_build(const float* __restrict__ adj) {
    int warp = threadIdx.x >> 5;
    int lane = threadIdx.x & 31;
    int m = blockIdx.x * 8 + warp;
    const float* row = adj + (size_t)m * NN;
    int* cl = g_col + m * DCAP;
    int base = 0;
    for (int j0 = 0; j0 < NN; j0 += 32) {
        int j = j0 + lane;
        float a = row[j];
        unsigned mask = __ballot_sync(0xffffffffu, a != 0.f);
        if (a != 0.f) {
            int pos = base + __popc(mask & ((1u << lane) - 1u));
            if (pos < DCAP) cl[pos] = j;
        }
        base += __popc(mask);
    }
    if (lane == 0) {
        g_len[m]  = base < DCAP ? base : DCAP;
        g_dinv[m] = (base > 0) ? rsqrtf((float)base) : 0.f;  // degree == nnz count
    }
}

// ---------------- K2: transpose x[B,C,N,T] -> h[n][f] (fp32 + bf16) ----------
__global__ void k_transpose(const float* __restrict__ x) {
    __shared__ float sm[32][193];
    int n0 = blockIdx.x * 16;
    int b  = blockIdx.y;
    for (int idx = threadIdx.x; idx < 32 * 192; idx += 256) {
        int c = idx / 192, r = idx % 192;   // r = n_local*12 + t
        sm[c][r] = x[(((size_t)(b * 32 + c)) * NN + n0) * TT + r];
    }
    __syncthreads();
    for (int idx = threadIdx.x; idx < 32 * 192; idx += 256) {
        int nl  = idx / 384;
        int rem = idx % 384;
        int t = rem >> 5;
        int c = rem & 31;
        float v = sm[c][nl * TT + t];
        size_t o = (size_t)(n0 + nl) * FF + (b * TT + t) * 32 + c;
        g_h [o] = v;
        g_hb[o] = __float2bfloat16_rn(v);
    }
}

// ---- helper: accumulate 8 bf16 (one uint4) into 8 fp32 accs -----------------
__device__ __forceinline__ void acc8(float* acc, uint4 v, float c) {
    __nv_bfloat162 b0 = *(__nv_bfloat162*)&v.x;
    __nv_bfloat162 b1 = *(__nv_bfloat162*)&v.y;
    __nv_bfloat162 b2 = *(__nv_bfloat162*)&v.z;
    __nv_bfloat162 b3 = *(__nv_bfloat162*)&v.w;
    float2 f0 = __bfloat1622float2(b0);
    float2 f1 = __bfloat1622float2(b1);
    float2 f2 = __bfloat1622float2(b2);
    float2 f3 = __bfloat1622float2(b3);
    acc[0] += c * f0.x; acc[1] += c * f0.y;
    acc[2] += c * f1.x; acc[3] += c * f1.y;
    acc[4] += c * f2.x; acc[5] += c * f2.y;
    acc[6] += c * f3.x; acc[7] += c * f3.y;
}

// ---------------- K3: Tx1 = h - norm_adj * h (bf16 gather) -------------------
// one block per row m; 192 threads x 8 features = full F=1536
__global__ void __launch_bounds__(192) k_spmm1() {
    int m  = blockIdx.x;
    int f0 = threadIdx.x * 8;
    __shared__ int   s_col[DCAP];
    __shared__ float s_val[DCAP];
    int len = g_len[m];
    float dm = g_dinv[m];
    for (int i = threadIdx.x; i < len; i += 192) {
        int j = g_col[m * DCAP + i];
        s_col[i] = j;
        s_val[i] = dm * g_dinv[j];
    }
    __syncthreads();

    float acc[8] = {0.f,0.f,0.f,0.f,0.f,0.f,0.f,0.f};
    const __nv_bfloat16* hb = g_hb;
    int i = 0;
    for (; i + 4 <= len; i += 4) {
        uint4 v0 = *(const uint4*)(hb + (size_t)s_col[i    ] * FF + f0);
        uint4 v1 = *(const uint4*)(hb + (size_t)s_col[i + 1] * FF + f0);
        uint4 v2 = *(const uint4*)(hb + (size_t)s_col[i + 2] * FF + f0);
        uint4 v3 = *(const uint4*)(hb + (size_t)s_col[i + 3] * FF + f0);
        acc8(acc, v0, s_val[i]);
        acc8(acc, v1, s_val[i + 1]);
        acc8(acc, v2, s_val[i + 2]);
        acc8(acc, v3, s_val[i + 3]);
    }
    for (; i < len; i++) {
        uint4 v = *(const uint4*)(hb + (size_t)s_col[i] * FF + f0);
        acc8(acc, v, s_val[i]);
    }

    size_t base = (size_t)m * FF + f0;
    float4 h0 = *(const float4*)(g_h + base);
    float4 h1 = *(const float4*)(g_h + base + 4);
    float r[8];
    r[0] = h0.x - acc[0]; r[1] = h0.y - acc[1];
    r[2] = h0.z - acc[2]; r[3] = h0.w - acc[3];
    r[4] = h1.x - acc[4]; r[5] = h1.y - acc[5];
    r[6] = h1.z - acc[6]; r[7] = h1.w - acc[7];
    *(float4*)(g_t1 + base)     = make_float4(r[0], r[1], r[2], r[3]);
    *(float4*)(g_t1 + base + 4) = make_float4(r[4], r[5], r[6], r[7]);
    uint4 o;
    *(__nv_bfloat162*)&o.x = __float22bfloat162_rn(make_float2(r[0], r[1]));
    *(__nv_bfloat162*)&o.y = __float22bfloat162_rn(make_float2(r[2], r[3]));
    *(__nv_bfloat162*)&o.z = __float22bfloat162_rn(make_float2(r[4], r[5]));
    *(__nv_bfloat162*)&o.w = __float22bfloat162_rn(make_float2(r[6], r[7]));
    *(uint4*)(g_t1b + base) = o;
}

// ---------------- K4: Tx2 = 2*(Tx1 - norm_adj*Tx1) - h (bf16 gather) ---------
__global__ void __launch_bounds__(192) k_spmm2() {
    int m  = blockIdx.x;
    int f0 = threadIdx.x * 8;
    __shared__ int   s_col[DCAP];
    __shared__ float s_val[DCAP];
    int len = g_len[m];
    float dm = g_dinv[m];
    for (int i = threadIdx.x; i < len; i += 192) {
        int j = g_col[m * DCAP + i];
        s_col[i] = j;
        s_val[i] = dm * g_dinv[j];
    }
    __syncthreads();

    float acc[8] = {0.f,0.f,0.f,0.f,0.f,0.f,0.f,0.f};
    const __nv_bfloat16* tb = g_t1b;
    int i = 0;
    for (; i + 4 <= len; i += 4) {
        uint4 v0 = *(const uint4*)(tb + (size_t)s_col[i    ] * FF + f0);
        uint4 v1 = *(const uint4*)(tb + (size_t)s_col[i + 1] * FF + f0);
        uint4 v2 = *(const uint4*)(tb + (size_t)s_col[i + 2] * FF + f0);
        uint4 v3 = *(const uint4*)(tb + (size_t)s_col[i + 3] * FF + f0);
        acc8(acc, v0, s_val[i]);
        acc8(acc, v1, s_val[i + 1]);
        acc8(acc, v2, s_val[i + 2]);
        acc8(acc, v3, s_val[i + 3]);
    }
    for (; i < len; i++) {
        uint4 v = *(const uint4*)(tb + (size_t)s_col[i] * FF + f0);
        acc8(acc, v, s_val[i]);
    }

    size_t base = (size_t)m * FF + f0;
    float4 t0 = *(const float4*)(g_t1 + base);
    float4 t1 = *(const float4*)(g_t1 + base + 4);
    float4 h0 = *(const float4*)(g_h  + base);
    float4 h1 = *(const float4*)(g_h  + base + 4);
    float4 r0, r1;
    r0.x = 2.f * (t0.x - acc[0]) - h0.x;
    r0.y = 2.f * (t0.y - acc[1]) - h0.y;
    r0.z = 2.f * (t0.z - acc[2]) - h0.z;
    r0.w = 2.f * (t0.w - acc[3]) - h0.w;
    r1.x = 2.f * (t1.x - acc[4]) - h1.x;
    r1.y = 2.f * (t1.y - acc[5]) - h1.y;
    r1.z = 2.f * (t1.z - acc[6]) - h1.z;
    r1.w = 2.f * (t1.w - acc[7]) - h1.w;
    *(float4*)(g_tx2 + base)     = r0;
    *(float4*)(g_tx2 + base + 4) = r1;
}

// ---------------- K5: out = Tx0*W0 + Tx1*W1 + Tx2*W2 + bias, transposed back -
__global__ void __launch_bounds__(384) k_out(const float* __restrict__ w,
                                             const float* __restrict__ bias,
                                             float* __restrict__ out) {
    __shared__ float sW[3 * 32 * 32];   // [k][c][co]
    __shared__ float sB[32];
    for (int idx = threadIdx.x; idx < 3 * 32 * 32; idx += 384) sW[idx] = w[idx];
    if (threadIdx.x < 32) sB[threadIdx.x] = bias[threadIdx.x];
    __syncthreads();

    int b  = blockIdx.y;
    int nl = threadIdx.x / 12;
    int t  = threadIdx.x % 12;
    int n  = blockIdx.x * 32 + nl;

    size_t fbase = (size_t)n * FF + (b * TT + t) * 32;
    const float* ph = g_h   + fbase;
    const float* p1 = g_t1  + fbase;
    const float* p2 = g_tx2 + fbase;

    float acc[32];
    #pragma unroll
    for (int co = 0; co < 32; co++) acc[co] = sB[co];

    #pragma unroll
    for (int c4 = 0; c4 < 8; c4++) {
        float4 A0 = *(const float4*)(ph + c4 * 4);
        float4 A1 = *(const float4*)(p1 + c4 * 4);
        float4 A2 = *(const float4*)(p2 + c4 * 4);
        #pragma unroll
        for (int cc = 0; cc < 4; cc++) {
            int c = c4 * 4 + cc;
            float a0 = ((const float*)&A0)[cc];
            float a1 = ((const float*)&A1)[cc];
            float a2 = ((const float*)&A2)[cc];
            const float4* w0 = (const float4*)(sW +            c * 32);
            const float4* w1 = (const float4*)(sW + 32 * 32 +  c * 32);
            const float4* w2 = (const float4*)(sW + 2*32*32 +  c * 32);
            #pragma unroll
            for (int q = 0; q < 8; q++) {
                float4 W0 = w0[q], W1 = w1[q], W2 = w2[q];
                acc[q*4+0] += a0*W0.x + a1*W1.x + a2*W2.x;
                acc[q*4+1] += a0*W0.y + a1*W1.y + a2*W2.y;
                acc[q*4+2] += a0*W0.z + a1*W1.z + a2*W2.z;
                acc[q*4+3] += a0*W0.w + a1*W1.w + a2*W2.w;
            }
        }
    }
    float* po = out + ((size_t)(b * 32) * NN + n) * TT + t;
    #pragma unroll
    for (int co = 0; co < 32; co++) po[(size_t)co * NN * TT] = acc[co];
}

// ---------------- launch -----------------------------------------------------
extern "C" void kernel_launch(void* const* d_in, const int* in_sizes, int n_in,
                              void* d_out, int out_size) {
    const float* x    = (const float*)d_in[0];   // [4,32,4096,12]
    const float* adj  = (const float*)d_in[1];   // [4096,4096]
    const float* w    = (const float*)d_in[2];   // [3,32,32]
    const float* bias = (const float*)d_in[3];   // [32]
    float* out = (float*)d_out;                  // [4,32,4096,12]

    k_build    <<<NN / 8, 256>>>(adj);
    k_transpose<<<dim3(NN / 16, BB), 256>>>(x);
    k_spmm1    <<<NN, 192>>>();
    k_spmm2    <<<NN, 192>>>();
    k_out      <<<dim3(NN / 32, BB), 384>>>(w, bias, out);
}

// round 6
// speedup vs baseline: 1.6042x; 1.6042x over previous
#include <cuda_runtime.h>
#include <cuda_bf16.h>
#include <cstddef>

// Problem constants
#define NN    4096          // nodes
#define BB    4             // batch
#define CC    32            // channels
#define TT    12            // time
#define FF    1536          // BT*C features per node
#define DCAP  256           // per-row neighbor capacity (max degree ~120)

// ---------------- scratch (device globals; no allocations allowed) ----------
__device__ float g_dinv[NN];
__device__ int   g_len [NN];
__device__ int   g_col [NN * DCAP];
__device__ float         g_h  [(size_t)NN * FF];   // fp32 master
__device__ float         g_t1 [(size_t)NN * FF];
__device__ float         g_tx2[(size_t)NN * FF];
__device__ __nv_bfloat16 g_hb [(size_t)NN * FF];   // bf16 gather shadows
__device__ __nv_bfloat16 g_t1b[(size_t)NN * FF];

// ---------------- K1: CSR build + degree (adj is exactly {0,1}) --------------
__global__ void k_build(const float* __restrict__ adj) {
    int warp = threadIdx.x >> 5;
    int lane = threadIdx.x & 31;
    int m = blockIdx.x * 8 + warp;
    const float* row = adj + (size_t)m * NN;
    int* cl = g_col + m * DCAP;
    int base = 0;
    for (int j0 = 0; j0 < NN; j0 += 32) {
        int j = j0 + lane;
        float a = row[j];
        unsigned mask = __ballot_sync(0xffffffffu, a != 0.f);
        if (a != 0.f) {
            int pos = base + __popc(mask & ((1u << lane) - 1u));
            if (pos < DCAP) cl[pos] = j;
        }
        base += __popc(mask);
    }
    if (lane == 0) {
        g_len[m]  = base < DCAP ? base : DCAP;
        g_dinv[m] = (base > 0) ? rsqrtf((float)base) : 0.f;  // degree == nnz count
    }
}

// ---------------- K2: transpose x[B,C,N,T] -> h[n][f] (fp32 + bf16) ----------
__global__ void k_transpose(const float* __restrict__ x) {
    __shared__ float sm[32][193];
    int n0 = blockIdx.x * 16;
    int b  = blockIdx.y;
    for (int idx = threadIdx.x; idx < 32 * 192; idx += 256) {
        int c = idx / 192, r = idx % 192;   // r = n_local*12 + t
        sm[c][r] = x[(((size_t)(b * 32 + c)) * NN + n0) * TT + r];
    }
    __syncthreads();
    for (int idx = threadIdx.x; idx < 32 * 192; idx += 256) {
        int nl  = idx / 384;
        int rem = idx % 384;
        int t = rem >> 5;
        int c = rem & 31;
        float v = sm[c][nl * TT + t];
        size_t o = (size_t)(n0 + nl) * FF + (b * TT + t) * 32 + c;
        g_h [o] = v;
        g_hb[o] = __float2bfloat16_rn(v);
    }
}

// ---- packed bf16x2 gather-accumulate: 8 features via 4 FFMA2 ----------------
// A[k] holds 2 fp32 accumulators. cc holds the coefficient in both halves.
__device__ __forceinline__ void acc8x2(unsigned long long* A, uint4 v,
                                       unsigned long long cc) {
    asm volatile("{\n\t"
        ".reg .b32 lo, hi;\n\t"
        ".reg .b64 vv;\n\t"
        "prmt.b32 lo, %1, 0, 0x1044;\n\t"
        "prmt.b32 hi, %1, 0, 0x3244;\n\t"
        "mov.b64 vv, {lo, hi};\n\t"
        "fma.rn.f32x2 %0, vv, %2, %0;\n\t"
        "}" : "+l"(A[0]) : "r"(v.x), "l"(cc));
    asm volatile("{\n\t"
        ".reg .b32 lo, hi;\n\t"
        ".reg .b64 vv;\n\t"
        "prmt.b32 lo, %1, 0, 0x1044;\n\t"
        "prmt.b32 hi, %1, 0, 0x3244;\n\t"
        "mov.b64 vv, {lo, hi};\n\t"
        "fma.rn.f32x2 %0, vv, %2, %0;\n\t"
        "}" : "+l"(A[1]) : "r"(v.y), "l"(cc));
    asm volatile("{\n\t"
        ".reg .b32 lo, hi;\n\t"
        ".reg .b64 vv;\n\t"
        "prmt.b32 lo, %1, 0, 0x1044;\n\t"
        "prmt.b32 hi, %1, 0, 0x3244;\n\t"
        "mov.b64 vv, {lo, hi};\n\t"
        "fma.rn.f32x2 %0, vv, %2, %0;\n\t"
        "}" : "+l"(A[2]) : "r"(v.z), "l"(cc));
    asm volatile("{\n\t"
        ".reg .b32 lo, hi;\n\t"
        ".reg .b64 vv;\n\t"
        "prmt.b32 lo, %1, 0, 0x1044;\n\t"
        "prmt.b32 hi, %1, 0, 0x3244;\n\t"
        "mov.b64 vv, {lo, hi};\n\t"
        "fma.rn.f32x2 %0, vv, %2, %0;\n\t"
        "}" : "+l"(A[3]) : "r"(v.w), "l"(cc));
}

__device__ __forceinline__ unsigned long long pack2(int bits) {
    unsigned long long r;
    asm("mov.b64 %0, {%1, %1};" : "=l"(r) : "r"(bits));
    return r;
}
__device__ __forceinline__ void unpack2(unsigned long long a, float& x, float& y) {
    asm("mov.b64 {%0, %1}, %2;" : "=f"(x), "=f"(y) : "l"(a));
}

// ---------------- K3: Tx1 = h - norm_adj * h (bf16 gather, f32x2 math) -------
__global__ void __launch_bounds__(192) k_spmm1() {
    int m   = blockIdx.x;
    int f0b = threadIdx.x * 16;            // byte offset of this thread's 8 bf16
    __shared__ int2 s_ent[DCAP];           // {byte offset of row, coef bits}
    int len = g_len[m];
    float dm = g_dinv[m];
    for (int i = threadIdx.x; i < len; i += 192) {
        int j = g_col[m * DCAP + i];
        s_ent[i] = make_int2(j * (FF * 2), __float_as_int(dm * g_dinv[j]));
    }
    __syncthreads();

    unsigned long long A[4] = {0ull, 0ull, 0ull, 0ull};
    const char* base = (const char*)g_hb;
    int i = 0;
    for (; i + 4 <= len; i += 4) {
        int2 e0 = s_ent[i], e1 = s_ent[i+1], e2 = s_ent[i+2], e3 = s_ent[i+3];
        uint4 v0 = *(const uint4*)(base + e0.x + f0b);
        uint4 v1 = *(const uint4*)(base + e1.x + f0b);
        uint4 v2 = *(const uint4*)(base + e2.x + f0b);
        uint4 v3 = *(const uint4*)(base + e3.x + f0b);
        acc8x2(A, v0, pack2(e0.y));
        acc8x2(A, v1, pack2(e1.y));
        acc8x2(A, v2, pack2(e2.y));
        acc8x2(A, v3, pack2(e3.y));
    }
    for (; i < len; i++) {
        int2 e = s_ent[i];
        uint4 v = *(const uint4*)(base + e.x + f0b);
        acc8x2(A, v, pack2(e.y));
    }

    float acc[8];
    unpack2(A[0], acc[0], acc[1]);
    unpack2(A[1], acc[2], acc[3]);
    unpack2(A[2], acc[4], acc[5]);
    unpack2(A[3], acc[6], acc[7]);

    size_t fbase = (size_t)m * FF + threadIdx.x * 8;
    float4 h0 = *(const float4*)(g_h + fbase);
    float4 h1 = *(const float4*)(g_h + fbase + 4);
    float r[8];
    r[0] = h0.x - acc[0]; r[1] = h0.y - acc[1];
    r[2] = h0.z - acc[2]; r[3] = h0.w - acc[3];
    r[4] = h1.x - acc[4]; r[5] = h1.y - acc[5];
    r[6] = h1.z - acc[6]; r[7] = h1.w - acc[7];
    *(float4*)(g_t1 + fbase)     = make_float4(r[0], r[1], r[2], r[3]);
    *(float4*)(g_t1 + fbase + 4) = make_float4(r[4], r[5], r[6], r[7]);
    uint4 o;
    *(__nv_bfloat162*)&o.x = __float22bfloat162_rn(make_float2(r[0], r[1]));
    *(__nv_bfloat162*)&o.y = __float22bfloat162_rn(make_float2(r[2], r[3]));
    *(__nv_bfloat162*)&o.z = __float22bfloat162_rn(make_float2(r[4], r[5]));
    *(__nv_bfloat162*)&o.w = __float22bfloat162_rn(make_float2(r[6], r[7]));
    *(uint4*)(g_t1b + fbase) = o;
}

// ---------------- K4: Tx2 = 2*(Tx1 - norm_adj*Tx1) - h -----------------------
__global__ void __launch_bounds__(192) k_spmm2() {
    int m   = blockIdx.x;
    int f0b = threadIdx.x * 16;
    __shared__ int2 s_ent[DCAP];
    int len = g_len[m];
    float dm = g_dinv[m];
    for (int i = threadIdx.x; i < len; i += 192) {
        int j = g_col[m * DCAP + i];
        s_ent[i] = make_int2(j * (FF * 2), __float_as_int(dm * g_dinv[j]));
    }
    __syncthreads();

    unsigned long long A[4] = {0ull, 0ull, 0ull, 0ull};
    const char* base = (const char*)g_t1b;
    int i = 0;
    for (; i + 4 <= len; i += 4) {
        int2 e0 = s_ent[i], e1 = s_ent[i+1], e2 = s_ent[i+2], e3 = s_ent[i+3];
        uint4 v0 = *(const uint4*)(base + e0.x + f0b);
        uint4 v1 = *(const uint4*)(base + e1.x + f0b);
        uint4 v2 = *(const uint4*)(base + e2.x + f0b);
        uint4 v3 = *(const uint4*)(base + e3.x + f0b);
        acc8x2(A, v0, pack2(e0.y));
        acc8x2(A, v1, pack2(e1.y));
        acc8x2(A, v2, pack2(e2.y));
        acc8x2(A, v3, pack2(e3.y));
    }
    for (; i < len; i++) {
        int2 e = s_ent[i];
        uint4 v = *(const uint4*)(base + e.x + f0b);
        acc8x2(A, v, pack2(e.y));
    }

    float acc[8];
    unpack2(A[0], acc[0], acc[1]);
    unpack2(A[1], acc[2], acc[3]);
    unpack2(A[2], acc[4], acc[5]);
    unpack2(A[3], acc[6], acc[7]);

    size_t fbase = (size_t)m * FF + threadIdx.x * 8;
    float4 t0 = *(const float4*)(g_t1 + fbase);
    float4 t1 = *(const float4*)(g_t1 + fbase + 4);
    float4 h0 = *(const float4*)(g_h  + fbase);
    float4 h1 = *(const float4*)(g_h  + fbase + 4);
    float4 r0, r1;
    r0.x = 2.f * (t0.x - acc[0]) - h0.x;
    r0.y = 2.f * (t0.y - acc[1]) - h0.y;
    r0.z = 2.f * (t0.z - acc[2]) - h0.z;
    r0.w = 2.f * (t0.w - acc[3]) - h0.w;
    r1.x = 2.f * (t1.x - acc[4]) - h1.x;
    r1.y = 2.f * (t1.y - acc[5]) - h1.y;
    r1.z = 2.f * (t1.z - acc[6]) - h1.z;
    r1.w = 2.f * (t1.w - acc[7]) - h1.w;
    *(float4*)(g_tx2 + fbase)     = r0;
    *(float4*)(g_tx2 + fbase + 4) = r1;
}

// ---------------- K5: out = Tx0*W0 + Tx1*W1 + Tx2*W2 + bias, transposed back -
__global__ void __launch_bounds__(384) k_out(const float* __restrict__ w,
                                             const float* __restrict__ bias,
                                             float* __restrict__ out) {
    __shared__ float sW[3 * 32 * 32];   // [k][c][co]
    __shared__ float sB[32];
    for (int idx = threadIdx.x; idx < 3 * 32 * 32; idx += 384) sW[idx] = w[idx];
    if (threadIdx.x < 32) sB[threadIdx.x] = bias[threadIdx.x];
    __syncthreads();

    int b  = blockIdx.y;
    int nl = threadIdx.x / 12;
    int t  = threadIdx.x % 12;
    int n  = blockIdx.x * 32 + nl;

    size_t fbase = (size_t)n * FF + (b * TT + t) * 32;
    const float* ph = g_h   + fbase;
    const float* p1 = g_t1  + fbase;
    const float* p2 = g_tx2 + fbase;

    float acc[32];
    #pragma unroll
    for (int co = 0; co < 32; co++) acc[co] = sB[co];

    #pragma unroll
    for (int c4 = 0; c4 < 8; c4++) {
        float4 A0 = *(const float4*)(ph + c4 * 4);
        float4 A1 = *(const float4*)(p1 + c4 * 4);
        float4 A2 = *(const float4*)(p2 + c4 * 4);
        #pragma unroll
        for (int cc = 0; cc < 4; cc++) {
            int c = c4 * 4 + cc;
            float a0 = ((const float*)&A0)[cc];
            float a1 = ((const float*)&A1)[cc];
            float a2 = ((const float*)&A2)[cc];
            const float4* w0 = (const float4*)(sW +            c * 32);
            const float4* w1 = (const float4*)(sW + 32 * 32 +  c * 32);
            const float4* w2 = (const float4*)(sW + 2*32*32 +  c * 32);
            #pragma unroll
            for (int q = 0; q < 8; q++) {
                float4 W0 = w0[q], W1 = w1[q], W2 = w2[q];
                acc[q*4+0] += a0*W0.x + a1*W1.x + a2*W2.x;
                acc[q*4+1] += a0*W0.y + a1*W1.y + a2*W2.y;
                acc[q*4+2] += a0*W0.z + a1*W1.z + a2*W2.z;
                acc[q*4+3] += a0*W0.w + a1*W1.w + a2*W2.w;
            }
        }
    }
    float* po = out + ((size_t)(b * 32) * NN + n) * TT + t;
    #pragma unroll
    for (int co = 0; co < 32; co++) po[(size_t)co * NN * TT] = acc[co];
}

// ---------------- launch -----------------------------------------------------
extern "C" void kernel_launch(void* const* d_in, const int* in_sizes, int n_in,
                              void* d_out, int out_size) {
    const float* x    = (const float*)d_in[0];   // [4,32,4096,12]
    const float* adj  = (const float*)d_in[1];   // [4096,4096]
    const float* w    = (const float*)d_in[2];   // [3,32,32]
    const float* bias = (const float*)d_in[3];   // [32]
    float* out = (float*)d_out;                  // [4,32,4096,12]

    k_build    <<<NN / 8, 256>>>(adj);
    k_transpose<<<dim3(NN / 16, BB), 256>>>(x);
    k_spmm1    <<<NN, 192>>>();
    k_spmm2    <<<NN, 192>>>();
    k_out      <<<dim3(NN / 32, BB), 384>>>(w, bias, out);
}